// round 1
// baseline (speedup 1.0000x reference)
#include <cuda_runtime.h>

// Network (after LIF degeneracy, alpha = expf(-200) == 0.0f exactly):
//   h = floor(relu(conv1(x, s2, k2)))  -> pool2   (1024, 8, 32, 32)
//   h = floor(relu(conv2(h, s1, k3p1)))-> pool2   (1024, 8, 16, 16)
//   h = floor(relu(conv3(h, s1, k3p1)))-> pool2   (1024, 8,  8,  8)
//   out = flatten(h) @ w_fc.T                      (1024, 2)   (readout LIF = identity)

#define SM_W2   0        // 576 floats
#define SM_W3   576      // 576
#define SM_WF   1152     // 1024
#define SM_P1   2176     // 8*34*34 = 9248  (zero-padded halo)
#define SM_P2   11424    // 8*18*18 = 2592  (zero-padded halo)
#define SM_P3   14016    // 512
#define SM_RD   14528    // 16
#define SM_TOT  14592    // floats -> 58368 bytes

__global__ __launch_bounds__(256, 2)
void snn_fused_kernel(const float* __restrict__ x,
                      const float* __restrict__ w1,
                      const float* __restrict__ w2,
                      const float* __restrict__ w3,
                      const float* __restrict__ wfc,
                      float* __restrict__ out)
{
    extern __shared__ float sm[];
    float* s_w2 = sm + SM_W2;
    float* s_w3 = sm + SM_W3;
    float* s_wf = sm + SM_WF;
    float* s_p1 = sm + SM_P1;   // [8][34][34], interior at +1
    float* s_p2 = sm + SM_P2;   // [8][18][18], interior at +1
    float* s_p3 = sm + SM_P3;   // [8][8][8] flat = reshape order c*64+y*8+x
    float* s_rd = sm + SM_RD;

    const int t    = threadIdx.x;
    const int n    = blockIdx.x;
    const int oc   = t >> 5;     // warp id = output channel (8 warps)
    const int lane = t & 31;

    // cooperative loads of weights + zero the padded tiles (borders must be 0)
    for (int i = t; i < 576; i += 256) { s_w2[i] = w2[i]; s_w3[i] = w3[i]; }
    for (int i = t; i < 1024; i += 256) s_wf[i] = wfc[i];
    for (int i = t; i < 9248; i += 256) s_p1[i] = 0.f;
    for (int i = t; i < 2592; i += 256) s_p2[i] = 0.f;

    // conv1 weights for this warp's oc: [ic*4 + dy*2 + dx]
    float w1r[8];
#pragma unroll
    for (int i = 0; i < 8; i++) w1r[i] = __ldg(&w1[oc * 8 + i]);

    __syncthreads();

    // ------------------------------------------------------------------
    // Stage A: conv1 (2x2, stride 2, no pad) + floor(relu) + maxpool2
    //   pooled output (oc, py, px) reads DISJOINT input patch
    //   rows 4py..4py+3, cols 4px..4px+3, both input channels.
    //   warp = fixed oc, lane = px (0..31) -> float4 loads, coalesced.
    // ------------------------------------------------------------------
    {
        const float* xn = x + (size_t)n * (2 * 128 * 128);
        const int px = lane;
#pragma unroll 1
        for (int py = 0; py < 32; py++) {
            float in0[16], in1[16];
#pragma unroll
            for (int r = 0; r < 4; r++) {
                float4 a = *(const float4*)(xn + (4 * py + r) * 128 + 4 * px);
                float4 b = *(const float4*)(xn + 16384 + (4 * py + r) * 128 + 4 * px);
                in0[r*4+0] = a.x; in0[r*4+1] = a.y; in0[r*4+2] = a.z; in0[r*4+3] = a.w;
                in1[r*4+0] = b.x; in1[r*4+1] = b.y; in1[r*4+2] = b.z; in1[r*4+3] = b.w;
            }
            float mx = -3.0e38f;
#pragma unroll
            for (int i = 0; i < 2; i++)
#pragma unroll
            for (int j = 0; j < 2; j++) {
                float c = 0.f;
#pragma unroll
                for (int dy = 0; dy < 2; dy++)
#pragma unroll
                for (int dx = 0; dx < 2; dx++) {
                    c = fmaf(in0[(2*i+dy)*4 + 2*j+dx], w1r[dy*2+dx],     c);
                    c = fmaf(in1[(2*i+dy)*4 + 2*j+dx], w1r[4 + dy*2+dx], c);
                }
                mx = fmaxf(mx, c);
            }
            s_p1[oc * 1156 + (py + 1) * 34 + (px + 1)] = floorf(fmaxf(mx, 0.f));
        }
    }
    __syncthreads();

    // ------------------------------------------------------------------
    // Stage B: conv2 (3x3, pad 1) + floor(relu) + maxpool2 on [8][32][32]
    //   warp = oc; thread handles 8 pooled positions p = lane + 32k.
    //   Pooled (py2,px2): conv outputs (2py2+i, 2px2+j) read logical rows
    //   2py2-1..2py2+2 -> physical (padded) rows 2py2..2py2+3.
    // ------------------------------------------------------------------
    {
        float acc[8][4];
#pragma unroll
        for (int k = 0; k < 8; k++)
#pragma unroll
            for (int q = 0; q < 4; q++) acc[k][q] = 0.f;

#pragma unroll 1
        for (int ic = 0; ic < 8; ic++) {
            float w[9];
#pragma unroll
            for (int q = 0; q < 9; q++) w[q] = s_w2[oc * 72 + ic * 9 + q]; // broadcast LDS
            const float* base = s_p1 + ic * 1156;
#pragma unroll
            for (int k = 0; k < 8; k++) {
                const int p = lane + 32 * k;
                const int py2 = p >> 4, px2 = p & 15;
                const float* bp = base + (2 * py2) * 34 + 2 * px2;
                float in[16];
#pragma unroll
                for (int r = 0; r < 4; r++)
#pragma unroll
                    for (int c = 0; c < 4; c++) in[r*4+c] = bp[r * 34 + c];
#pragma unroll
                for (int i = 0; i < 2; i++)
#pragma unroll
                for (int j = 0; j < 2; j++)
#pragma unroll
                    for (int ky = 0; ky < 3; ky++)
#pragma unroll
                        for (int kx = 0; kx < 3; kx++)
                            acc[k][i*2+j] = fmaf(in[(i+ky)*4 + (j+kx)], w[ky*3+kx], acc[k][i*2+j]);
            }
        }
#pragma unroll
        for (int k = 0; k < 8; k++) {
            const int p = lane + 32 * k;
            const int py2 = p >> 4, px2 = p & 15;
            float mx = fmaxf(fmaxf(acc[k][0], acc[k][1]), fmaxf(acc[k][2], acc[k][3]));
            s_p2[oc * 324 + (py2 + 1) * 18 + (px2 + 1)] = floorf(fmaxf(mx, 0.f));
        }
    }
    __syncthreads();

    // ------------------------------------------------------------------
    // Stage C: conv3 (3x3, pad 1) + floor(relu) + maxpool2 on [8][16][16]
    //   thread handles 2 pooled positions p = lane + 32k (64 positions).
    // ------------------------------------------------------------------
    {
        float acc[2][4];
#pragma unroll
        for (int k = 0; k < 2; k++)
#pragma unroll
            for (int q = 0; q < 4; q++) acc[k][q] = 0.f;

#pragma unroll 1
        for (int ic = 0; ic < 8; ic++) {
            float w[9];
#pragma unroll
            for (int q = 0; q < 9; q++) w[q] = s_w3[oc * 72 + ic * 9 + q];
            const float* base = s_p2 + ic * 324;
#pragma unroll
            for (int k = 0; k < 2; k++) {
                const int p = lane + 32 * k;
                const int py3 = p >> 3, px3 = p & 7;
                const float* bp = base + (2 * py3) * 18 + 2 * px3;
                float in[16];
#pragma unroll
                for (int r = 0; r < 4; r++)
#pragma unroll
                    for (int c = 0; c < 4; c++) in[r*4+c] = bp[r * 18 + c];
#pragma unroll
                for (int i = 0; i < 2; i++)
#pragma unroll
                for (int j = 0; j < 2; j++)
#pragma unroll
                    for (int ky = 0; ky < 3; ky++)
#pragma unroll
                        for (int kx = 0; kx < 3; kx++)
                            acc[k][i*2+j] = fmaf(in[(i+ky)*4 + (j+kx)], w[ky*3+kx], acc[k][i*2+j]);
            }
        }
#pragma unroll
        for (int k = 0; k < 2; k++) {
            const int p = lane + 32 * k;
            const int py3 = p >> 3, px3 = p & 7;
            float mx = fmaxf(fmaxf(acc[k][0], acc[k][1]), fmaxf(acc[k][2], acc[k][3]));
            s_p3[oc * 64 + py3 * 8 + px3] = floorf(fmaxf(mx, 0.f));
        }
    }
    __syncthreads();

    // ------------------------------------------------------------------
    // Stage D: FC 512 -> 2 (readout LIF = identity)
    // ------------------------------------------------------------------
    {
        float a0 = 0.f, a1 = 0.f;
        for (int i = t; i < 512; i += 256) {  // 2 iterations
            const float v = s_p3[i];
            a0 = fmaf(v, s_wf[i], a0);
            a1 = fmaf(v, s_wf[512 + i], a1);
        }
#pragma unroll
        for (int o = 16; o > 0; o >>= 1) {
            a0 += __shfl_xor_sync(0xffffffffu, a0, o);
            a1 += __shfl_xor_sync(0xffffffffu, a1, o);
        }
        if (lane == 0) { s_rd[oc] = a0; s_rd[8 + oc] = a1; }
        __syncthreads();
        if (t == 0) {
            float b0 = 0.f, b1 = 0.f;
#pragma unroll
            for (int w = 0; w < 8; w++) { b0 += s_rd[w]; b1 += s_rd[8 + w]; }
            out[n * 2 + 0] = b0;
            out[n * 2 + 1] = b1;
        }
    }
}

extern "C" void kernel_launch(void* const* d_in, const int* in_sizes, int n_in,
                              void* d_out, int out_size)
{
    (void)in_sizes; (void)n_in; (void)out_size;
    const float* x   = (const float*)d_in[0];
    const float* w1  = (const float*)d_in[1];
    const float* w2  = (const float*)d_in[2];
    const float* w3  = (const float*)d_in[3];
    const float* wfc = (const float*)d_in[4];
    float* out = (float*)d_out;

    const size_t smem = SM_TOT * sizeof(float);  // 58368 B > 48KB default
    cudaFuncSetAttribute(snn_fused_kernel,
                         cudaFuncAttributeMaxDynamicSharedMemorySize, (int)smem);
    snn_fused_kernel<<<1024, 256, smem>>>(x, w1, w2, w3, wfc, out);
}

// round 2
// speedup vs baseline: 1.9738x; 1.9738x over previous
#include <cuda_runtime.h>

// SmartDoorClassifier — LIF degeneracy: alpha = exp(-200) == 0.0f in fp32, so
// every LIF is memoryless:  spiking LIF == floor(relu(.)), readout LIF == identity.
// Net: conv1(2x2,s2) -> fr -> pool2 -> conv2(3x3,p1) -> fr -> pool2
//      -> conv3(3x3,p1) -> fr -> pool2 -> FC(512->2).
// floor∘relu commutes with max-pool, so we pool raw conv outputs then apply it once.

#define RS1 48            // p1 row stride (floats), 36 used + pad for swizzle
#define PS1 (34*RS1)      // 1632 floats per ic plane (34 rows incl. halo)
#define RS2 20            // p2 row stride, 18 used
#define PS2 (18*RS2)      // 360

#define SW2 0             // 576 floats (conv2 weights)
#define SW3 576           // 576
#define SWF 1152          // 1024 (fc weights)
#define P1  2176          // 8*PS1 = 13056
#define P2  (P1 + 8*PS1)  // 15232, 8*PS2 = 2880
#define P3  (P2 + 8*PS2)  // 18112, 512
#define RD  (P3 + 512)    // 18624, 16
#define TOT (RD + 16)     // 18640 floats = 74560 bytes

// 16B-chunk XOR swizzle on p1 columns, keyed on row-pair. Makes stage-B LDS.128
// phases (lanes = (py2 0..3, half 0..1)) hit 8 distinct 16B bank groups.
__device__ __forceinline__ int sw1c(int row, int chunk) {
    return chunk ^ ((row >> 1) & 3);
}

__global__ __launch_bounds__(256, 2)
void snn_fused_kernel(const float* __restrict__ x,
                      const float* __restrict__ w1,
                      const float* __restrict__ w2,
                      const float* __restrict__ w3,
                      const float* __restrict__ wfc,
                      float* __restrict__ out)
{
    extern __shared__ float sm[];
    const int t    = threadIdx.x;
    const int n    = blockIdx.x;
    const int lane = t & 31;

    // ---- init: weights to smem, zero p1+p2 (halo must be 0) -------------
    for (int i = t; i < 576; i += 256) { sm[SW2 + i] = w2[i]; sm[SW3 + i] = w3[i]; }
    for (int i = t; i < 1024; i += 256) sm[SWF + i] = wfc[i];
    {   // p1 (13056) and p2 (2880) are contiguous: zero 15936 floats as float4
        float4 z = make_float4(0.f, 0.f, 0.f, 0.f);
        float4* zp = (float4*)(sm + P1);
        for (int i = t; i < (8 * PS1 + 8 * PS2) / 4; i += 256) zp[i] = z;
    }

    // conv1 weights, all 8 oc, in registers: w1[oc*8 + ch*4 + dy*2 + dx]
    float w1r[64];
#pragma unroll
    for (int i = 0; i < 64; i++) w1r[i] = __ldg(&w1[i]);

    __syncthreads();

    // ------------------------------------------------------------------
    // Stage A: conv1 + floor(relu) + pool2 -> p1[8][32][32] (padded, swizzled)
    // Thread = pooled position (px=lane, py=warp+8k); computes ALL 8 oc.
    // Each input element is read exactly once per CTA (coalesced float4).
    // ------------------------------------------------------------------
    {
        const float* xn = x + (size_t)n * 32768;
        const int px = lane, py0 = t >> 5;
#pragma unroll 1
        for (int k = 0; k < 4; k++) {
            const int py = py0 + 8 * k;
            float A0[16], A1[16];
#pragma unroll
            for (int r = 0; r < 4; r++) {
                float4 a = *(const float4*)(xn + (4 * py + r) * 128 + 4 * px);
                float4 b = *(const float4*)(xn + 16384 + (4 * py + r) * 128 + 4 * px);
                A0[r*4+0]=a.x; A0[r*4+1]=a.y; A0[r*4+2]=a.z; A0[r*4+3]=a.w;
                A1[r*4+0]=b.x; A1[r*4+1]=b.y; A1[r*4+2]=b.z; A1[r*4+3]=b.w;
            }
            const int row = py + 1;
            const int col = px + 1;
            const int caddr = (sw1c(row, col >> 2) << 2) | (col & 3);
            float* dst = sm + P1 + row * RS1 + caddr;
#pragma unroll
            for (int oc = 0; oc < 8; oc++) {
                float mx = -3.0e38f;
#pragma unroll
                for (int i = 0; i < 2; i++)
#pragma unroll
                for (int j = 0; j < 2; j++) {
                    float c = 0.f;
#pragma unroll
                    for (int dy = 0; dy < 2; dy++)
#pragma unroll
                    for (int dx = 0; dx < 2; dx++) {
                        c = fmaf(A0[(2*i+dy)*4 + 2*j+dx], w1r[oc*8 +     dy*2+dx], c);
                        c = fmaf(A1[(2*i+dy)*4 + 2*j+dx], w1r[oc*8 + 4 + dy*2+dx], c);
                    }
                    mx = fmaxf(mx, c);
                }
                dst[oc * PS1] = floorf(fmaxf(mx, 0.f));
            }
        }
    }
    __syncthreads();

    // ------------------------------------------------------------------
    // Stage B: conv2 + floor(relu) + pool2 -> p2[8][16][16] (padded)
    // warp = oc; lane = (py2 = lane>>1, half = lane&1) -> 8 contiguous pooled
    // cols. Rows loaded as float4+float4+float2 from swizzled p1.
    // ------------------------------------------------------------------
    {
        const int oc  = t >> 5;
        const int py2 = lane >> 1, half = lane & 1;
        float acc[8][4];
#pragma unroll
        for (int j = 0; j < 8; j++)
#pragma unroll
            for (int q = 0; q < 4; q++) acc[j][q] = 0.f;

#pragma unroll 1
        for (int ic = 0; ic < 8; ic++) {
            float w[9];
#pragma unroll
            for (int q = 0; q < 9; q++) w[q] = sm[SW2 + oc * 72 + ic * 9 + q];
            const float* plane = sm + P1 + ic * PS1;
#pragma unroll
            for (int g = 0; g < 2; g++) {
                const int c0 = 4 * half + 2 * g;   // window start chunk
                float in[4][10];
#pragma unroll
                for (int r = 0; r < 4; r++) {
                    const int row = 2 * py2 + r;
                    const float* rp = plane + row * RS1;
                    float4 v0 = *(const float4*)(rp + (sw1c(row, c0)     << 2));
                    float4 v1 = *(const float4*)(rp + (sw1c(row, c0 + 1) << 2));
                    float2 v2 = *(const float2*)(rp + (sw1c(row, c0 + 2) << 2));
                    in[r][0]=v0.x; in[r][1]=v0.y; in[r][2]=v0.z; in[r][3]=v0.w;
                    in[r][4]=v1.x; in[r][5]=v1.y; in[r][6]=v1.z; in[r][7]=v1.w;
                    in[r][8]=v2.x; in[r][9]=v2.y;
                }
#pragma unroll
                for (int j = 0; j < 4; j++)
#pragma unroll
                for (int i = 0; i < 2; i++)
#pragma unroll
                for (int jj = 0; jj < 2; jj++) {
                    const int cc = 2 * j + jj;
                    float s = acc[g*4 + j][i*2 + jj];
#pragma unroll
                    for (int ky = 0; ky < 3; ky++)
#pragma unroll
                        for (int kx = 0; kx < 3; kx++)
                            s = fmaf(in[i + ky][cc + kx], w[ky*3 + kx], s);
                    acc[g*4 + j][i*2 + jj] = s;
                }
            }
        }
#pragma unroll
        for (int j = 0; j < 8; j++) {
            const int px2 = half * 8 + j;
            float mx = fmaxf(fmaxf(acc[j][0], acc[j][1]), fmaxf(acc[j][2], acc[j][3]));
            sm[P2 + oc * PS2 + (py2 + 1) * RS2 + (px2 + 1)] = floorf(fmaxf(mx, 0.f));
        }
    }
    __syncthreads();

    // ------------------------------------------------------------------
    // Stage C: conv3 + floor(relu) + pool2 -> p3[8][8][8]
    // warp = oc; lane = (py3 = lane>>2, q = lane&3) -> 2 pooled cols {2q,2q+1}.
    // ------------------------------------------------------------------
    {
        const int oc  = t >> 5;
        const int py3 = lane >> 2, q = lane & 3;
        float acc[2][4];
#pragma unroll
        for (int j = 0; j < 2; j++)
#pragma unroll
            for (int p = 0; p < 4; p++) acc[j][p] = 0.f;

#pragma unroll 1
        for (int ic = 0; ic < 8; ic++) {
            float w[9];
#pragma unroll
            for (int p = 0; p < 9; p++) w[p] = sm[SW3 + oc * 72 + ic * 9 + p];
            const float* plane = sm + P2 + ic * PS2;
            float in[4][6];
#pragma unroll
            for (int r = 0; r < 4; r++) {
                const float* rp = plane + (2 * py3 + r) * RS2 + 4 * q;
                float4 v0 = *(const float4*)(rp);
                float2 v1 = *(const float2*)(rp + 4);
                in[r][0]=v0.x; in[r][1]=v0.y; in[r][2]=v0.z; in[r][3]=v0.w;
                in[r][4]=v1.x; in[r][5]=v1.y;
            }
#pragma unroll
            for (int j = 0; j < 2; j++)
#pragma unroll
            for (int i = 0; i < 2; i++)
#pragma unroll
            for (int jj = 0; jj < 2; jj++) {
                const int cc = 2 * j + jj;
                float s = acc[j][i*2 + jj];
#pragma unroll
                for (int ky = 0; ky < 3; ky++)
#pragma unroll
                    for (int kx = 0; kx < 3; kx++)
                        s = fmaf(in[i + ky][cc + kx], w[ky*3 + kx], s);
                acc[j][i*2 + jj] = s;
            }
        }
#pragma unroll
        for (int j = 0; j < 2; j++) {
            const int px3 = 2 * q + j;
            float mx = fmaxf(fmaxf(acc[j][0], acc[j][1]), fmaxf(acc[j][2], acc[j][3]));
            sm[P3 + oc * 64 + py3 * 8 + px3] = floorf(fmaxf(mx, 0.f));
        }
    }
    __syncthreads();

    // ------------------------------------------------------------------
    // Stage D: FC 512 -> 2 (readout LIF = identity)
    // ------------------------------------------------------------------
    {
        const int oc = t >> 5;
        float a0 = 0.f, a1 = 0.f;
        for (int i = t; i < 512; i += 256) {
            const float v = sm[P3 + i];
            a0 = fmaf(v, sm[SWF + i],       a0);
            a1 = fmaf(v, sm[SWF + 512 + i], a1);
        }
#pragma unroll
        for (int o = 16; o > 0; o >>= 1) {
            a0 += __shfl_xor_sync(0xffffffffu, a0, o);
            a1 += __shfl_xor_sync(0xffffffffu, a1, o);
        }
        if (lane == 0) { sm[RD + oc] = a0; sm[RD + 8 + oc] = a1; }
        __syncthreads();
        if (t == 0) {
            float b0 = 0.f, b1 = 0.f;
#pragma unroll
            for (int w = 0; w < 8; w++) { b0 += sm[RD + w]; b1 += sm[RD + 8 + w]; }
            out[n * 2 + 0] = b0;
            out[n * 2 + 1] = b1;
        }
    }
}

extern "C" void kernel_launch(void* const* d_in, const int* in_sizes, int n_in,
                              void* d_out, int out_size)
{
    (void)in_sizes; (void)n_in; (void)out_size;
    const float* x   = (const float*)d_in[0];
    const float* w1  = (const float*)d_in[1];
    const float* w2  = (const float*)d_in[2];
    const float* w3  = (const float*)d_in[3];
    const float* wfc = (const float*)d_in[4];
    float* outp = (float*)d_out;

    const size_t smem = TOT * sizeof(float);   // 74560 B
    cudaFuncSetAttribute(snn_fused_kernel,
                         cudaFuncAttributeMaxDynamicSharedMemorySize, (int)smem);
    snn_fused_kernel<<<1024, 256, smem>>>(x, w1, w2, w3, wfc, outp);
}

// round 3
// speedup vs baseline: 2.0922x; 1.0600x over previous
#include <cuda_runtime.h>

// SmartDoorClassifier — LIF degeneracy (alpha = exp(-200) == 0.0f in fp32):
// spiking LIF == floor(relu(.)), readout LIF == identity, scan collapses.
// conv1(2x2,s2)->fr->pool2 -> conv2(3x3,p1)->fr->pool2 -> conv3(3x3,p1)->fr->pool2 -> FC.
// conv2/conv3 use fp32x2 packed FMA (FFMA2) along the input-channel axis:
// activations stored as ic-pair-interleaved float2 elements, weights pre-packed.

#define SW2 0                 // 576 floats: conv2 weights packed [oc][icp][9] x float2
#define SW3 576               // 576: conv3 likewise
#define SWF 1152              // 1024: fc weights
#define P1  2176              // 4 icp-planes x 34 rows x 48 elems x 2 fl = 13056
#define P2  15232             // 4 x 18 x 20 x 2 = 2880
#define P3  18112             // 512
#define RD  18624             // 16
#define TOT 18640             // floats -> 74560 bytes

#define PS1 3264              // p1 plane stride (floats) = 34*96
#define RS1 96                // p1 row stride (floats)   = 48 elems
#define PS2 720               // p2 plane stride = 18*40
#define RS2 40                // p2 row stride   = 20 elems

typedef unsigned long long u64;

__device__ __forceinline__ void fma2(u64& d, u64 a, u64 b) {
    asm("fma.rn.f32x2 %0, %1, %2, %0;" : "+l"(d) : "l"(a), "l"(b));
}
__device__ __forceinline__ void upk(u64 d, float& lo, float& hi) {
    asm("mov.b64 {%0, %1}, %2;" : "=f"(lo), "=f"(hi) : "l"(d));
}

__global__ __launch_bounds__(256, 2)
void snn_fused_kernel(const float* __restrict__ x,
                      const float* __restrict__ w1,
                      const float* __restrict__ w2,
                      const float* __restrict__ w3,
                      const float* __restrict__ wfc,
                      float* __restrict__ out)
{
    extern __shared__ float sm[];
    const int t    = threadIdx.x;
    const int n    = blockIdx.x;
    const int lane = t & 31;

    // ---- init: packed weights + zero p1/p2 (halo must be 0) -------------
    for (int i = t; i < 288; i += 256) {
        const int oc = i / 36, icp = (i % 36) / 9, q = i % 9;
        const int b = oc * 72 + icp * 18 + q;
        ((float2*)(sm + SW2))[i] = make_float2(w2[b], w2[b + 9]);
        ((float2*)(sm + SW3))[i] = make_float2(w3[b], w3[b + 9]);
    }
    for (int i = t; i < 1024; i += 256) sm[SWF + i] = wfc[i];
    {
        float4 z = make_float4(0.f, 0.f, 0.f, 0.f);
        float4* zp = (float4*)(sm + P1);
        for (int i = t; i < (13056 + 2880) / 4; i += 256) zp[i] = z;
    }

    float w1r[64];
#pragma unroll
    for (int i = 0; i < 64; i++) w1r[i] = __ldg(&w1[i]);
    __syncthreads();

    // ------------------------------------------------------------------
    // Stage A: conv1 + floor(relu) + pool2 -> p1 (icp-packed, swizzled)
    // Thread = pooled position (px=lane, py=warp+8k), computes all 8 oc.
    // ------------------------------------------------------------------
    {
        const float* xn = x + (size_t)n * 32768;
        const int px = lane, py0 = t >> 5;
#pragma unroll 1
        for (int k = 0; k < 4; k++) {
            const int py = py0 + 8 * k;
            float A0[16], A1[16];
#pragma unroll
            for (int r = 0; r < 4; r++) {
                float4 a = *(const float4*)(xn + (4 * py + r) * 128 + 4 * px);
                float4 b = *(const float4*)(xn + 16384 + (4 * py + r) * 128 + 4 * px);
                A0[r*4+0]=a.x; A0[r*4+1]=a.y; A0[r*4+2]=a.z; A0[r*4+3]=a.w;
                A1[r*4+0]=b.x; A1[r*4+1]=b.y; A1[r*4+2]=b.z; A1[r*4+3]=b.w;
            }
            float o[8];
#pragma unroll
            for (int oc = 0; oc < 8; oc++) {
                float mx = -3.0e38f;
#pragma unroll
                for (int i = 0; i < 2; i++)
#pragma unroll
                for (int j = 0; j < 2; j++) {
                    float c = 0.f;
#pragma unroll
                    for (int dy = 0; dy < 2; dy++)
#pragma unroll
                    for (int dx = 0; dx < 2; dx++) {
                        c = fmaf(A0[(2*i+dy)*4 + 2*j+dx], w1r[oc*8 +     dy*2+dx], c);
                        c = fmaf(A1[(2*i+dy)*4 + 2*j+dx], w1r[oc*8 + 4 + dy*2+dx], c);
                    }
                    mx = fmaxf(mx, c);
                }
                o[oc] = floorf(fmaxf(mx, 0.f));
            }
            const int row = py + 1, col = px + 1;
            const int key = (row >> 1) & 7;
            const int chunk = col >> 1;
            const int phys = (chunk & ~7) | ((chunk & 7) ^ key);
            const int eoff = row * RS1 + (phys * 2 + (col & 1)) * 2;
#pragma unroll
            for (int icp = 0; icp < 4; icp++)
                *(float2*)(sm + P1 + icp * PS1 + eoff) = make_float2(o[2*icp], o[2*icp+1]);
        }
    }
    __syncthreads();

    // ------------------------------------------------------------------
    // Stage B: conv2 + floor(relu) + pool2 -> p2 (icp-packed)
    // warp = oc; lane = half*16 + py2 (py2 = pooled row 0..15, half = col group)
    // FFMA2: acc = {sum over even ic, sum over odd ic}; summed at the end.
    // ------------------------------------------------------------------
    {
        const int oc  = t >> 5;
        const int py2 = lane & 15, half = lane >> 4;
#pragma unroll 1
        for (int g = 0; g < 2; g++) {
            u64 acc[16];           // [jp][cell(i*2+jj)]
#pragma unroll
            for (int i = 0; i < 16; i++) acc[i] = 0ull;

            const int c0 = 8 * half + 4 * g;   // window start chunk
#pragma unroll 1
            for (int icp = 0; icp < 4; icp++) {
                u64 w[9];
#pragma unroll
                for (int q = 0; q < 9; q++)
                    w[q] = *(const u64*)(sm + SW2 + (oc * 36 + icp * 9 + q) * 2);
                const float* plane = sm + P1 + icp * PS1;
#pragma unroll
                for (int r = 0; r < 4; r++) {
                    const int row = 2 * py2 + r;
                    const int key = (row >> 1) & 7;
                    const float* rp = plane + row * RS1;
                    u64 e[10];
#pragma unroll
                    for (int k = 0; k < 5; k++) {
                        const int c = c0 + k;
                        const int phys = (c & ~7) | ((c & 7) ^ key);
                        ulonglong2 v = *(const ulonglong2*)(rp + phys * 4);
                        e[2*k] = v.x; e[2*k+1] = v.y;
                    }
#pragma unroll
                    for (int ky = 0; ky < 3; ky++) {
                        const int i = r - ky;
                        if (i >= 0 && i <= 1) {
#pragma unroll
                            for (int jp = 0; jp < 4; jp++)
#pragma unroll
                            for (int jj = 0; jj < 2; jj++)
#pragma unroll
                            for (int kx = 0; kx < 3; kx++)
                                fma2(acc[jp*4 + i*2 + jj], e[2*jp + jj + kx], w[ky*3 + kx]);
                        }
                    }
                }
            }
            // epilogue: sum halves, pool, floor(relu), store (oc-parity packed)
            const int row2 = py2 + 1;
            const int key2 = (row2 >> 1) & 1;
#pragma unroll
            for (int jp = 0; jp < 4; jp++) {
                float s[4];
#pragma unroll
                for (int c = 0; c < 4; c++) {
                    float lo, hi; upk(acc[jp*4 + c], lo, hi); s[c] = lo + hi;
                }
                float mx = fmaxf(fmaxf(s[0], s[1]), fmaxf(s[2], s[3]));
                const int px2 = half * 8 + g * 4 + jp;
                const int e2 = px2 + 1;
                const int pe = (((e2 >> 1) ^ key2) << 1) | (e2 & 1);
                sm[P2 + (oc >> 1) * PS2 + row2 * RS2 + pe * 2 + (oc & 1)]
                    = floorf(fmaxf(mx, 0.f));
            }
        }
    }
    __syncthreads();

    // ------------------------------------------------------------------
    // Stage C: conv3 + floor(relu) + pool2 -> p3[8][8][8]
    // warp = oc; lane = py3*4 + q (py3 = pooled row, q -> cols 2q, 2q+1)
    // ------------------------------------------------------------------
    {
        const int oc  = t >> 5;
        const int py3 = lane >> 2, q = lane & 3;
        u64 acc[8];   // [j][cell]
#pragma unroll
        for (int i = 0; i < 8; i++) acc[i] = 0ull;

#pragma unroll 1
        for (int icp = 0; icp < 4; icp++) {
            u64 w[9];
#pragma unroll
            for (int p = 0; p < 9; p++)
                w[p] = *(const u64*)(sm + SW3 + (oc * 36 + icp * 9 + p) * 2);
            const float* plane = sm + P2 + icp * PS2;
#pragma unroll
            for (int r = 0; r < 4; r++) {
                const int row = 2 * py3 + r;
                const int key = (row >> 1) & 1;
                const float* rp = plane + row * RS2;
                u64 e[6];
#pragma unroll
                for (int k = 0; k < 3; k++) {
                    const int phys = (2 * q + k) ^ key;
                    ulonglong2 v = *(const ulonglong2*)(rp + phys * 4);
                    e[2*k] = v.x; e[2*k+1] = v.y;
                }
#pragma unroll
                for (int ky = 0; ky < 3; ky++) {
                    const int i = r - ky;
                    if (i >= 0 && i <= 1) {
#pragma unroll
                        for (int j = 0; j < 2; j++)
#pragma unroll
                        for (int jj = 0; jj < 2; jj++)
#pragma unroll
                        for (int kx = 0; kx < 3; kx++)
                            fma2(acc[j*4 + i*2 + jj], e[2*j + jj + kx], w[ky*3 + kx]);
                    }
                }
            }
        }
#pragma unroll
        for (int j = 0; j < 2; j++) {
            float s[4];
#pragma unroll
            for (int c = 0; c < 4; c++) {
                float lo, hi; upk(acc[j*4 + c], lo, hi); s[c] = lo + hi;
            }
            float mx = fmaxf(fmaxf(s[0], s[1]), fmaxf(s[2], s[3]));
            sm[P3 + oc * 64 + py3 * 8 + 2 * q + j] = floorf(fmaxf(mx, 0.f));
        }
    }
    __syncthreads();

    // ------------------------------------------------------------------
    // Stage D: FC 512 -> 2 (readout LIF = identity)
    // ------------------------------------------------------------------
    {
        const int oc = t >> 5;
        float a0 = 0.f, a1 = 0.f;
        for (int i = t; i < 512; i += 256) {
            const float v = sm[P3 + i];
            a0 = fmaf(v, sm[SWF + i],       a0);
            a1 = fmaf(v, sm[SWF + 512 + i], a1);
        }
#pragma unroll
        for (int o = 16; o > 0; o >>= 1) {
            a0 += __shfl_xor_sync(0xffffffffu, a0, o);
            a1 += __shfl_xor_sync(0xffffffffu, a1, o);
        }
        if (lane == 0) { sm[RD + oc] = a0; sm[RD + 8 + oc] = a1; }
        __syncthreads();
        if (t == 0) {
            float b0 = 0.f, b1 = 0.f;
#pragma unroll
            for (int w = 0; w < 8; w++) { b0 += sm[RD + w]; b1 += sm[RD + 8 + w]; }
            out[n * 2 + 0] = b0;
            out[n * 2 + 1] = b1;
        }
    }
}

extern "C" void kernel_launch(void* const* d_in, const int* in_sizes, int n_in,
                              void* d_out, int out_size)
{
    (void)in_sizes; (void)n_in; (void)out_size;
    const float* x   = (const float*)d_in[0];
    const float* w1  = (const float*)d_in[1];
    const float* w2  = (const float*)d_in[2];
    const float* w3  = (const float*)d_in[3];
    const float* wfc = (const float*)d_in[4];
    float* outp = (float*)d_out;

    const size_t smem = TOT * sizeof(float);   // 74560 B
    cudaFuncSetAttribute(snn_fused_kernel,
                         cudaFuncAttributeMaxDynamicSharedMemorySize, (int)smem);
    snn_fused_kernel<<<1024, 256, smem>>>(x, w1, w2, w3, wfc, outp);
}